// round 7
// baseline (speedup 1.0000x reference)
#include <cuda_runtime.h>
#include <math.h>
#include <cstdint>

#define HH 384
#define CC 192
#define WSZ 8
#define SHIFTV 4
#define NHEADS 6
#define HDIM 32
#define NTOK 64
#define NWIN 2304
#define TT 147456

// -------- scratch (device globals) --------
__device__ float g_q[NWIN*NHEADS*NTOK*HDIM];
__device__ float g_k[NWIN*NHEADS*NTOK*HDIM];
__device__ float g_v[NWIN*NHEADS*NTOK*HDIM];
__device__ float g_ctx[TT*CC];      // attention out (tf32-rounded), window order
__device__ float g_xattn[TT*CC];    // proj out, image order (fp32)
__device__ float g_h[TT*CC];        // shortcut + LN1 (fp32, residual)
__device__ float g_h32[TT*CC];      // tf32 shadow of g_h (GEMM A)
__device__ float g_hid32[TT*CC];    // tf32-rounded hidden
__device__ float g_mid[TT*2*CC];    // gelu(fc1) (tf32-rounded)
__device__ float g_mlp[TT*CC];      // fc2 out (fp32)
__device__ float g_rpb[NHEADS*NTOK*NTOK];
__device__ float g_btab[225*NHEADS];
// transposed tf32 weights [N, K] K-major
__device__ float g_wtq[CC*CC];
__device__ float g_wtk[CC*CC];
__device__ float g_wtv[CC*CC];
__device__ float g_wtp[CC*CC];
__device__ float g_wt1[2*CC*CC];    // [384, 192]
__device__ float g_wt2[CC*2*CC];    // [192, 384]

__device__ __forceinline__ uint32_t f2tf32(float x) {
    uint32_t r;
    asm("cvt.rna.tf32.f32 %0, %1;" : "=r"(r) : "f"(x));
    return r;
}
__device__ __forceinline__ float rtf(float x) { return __uint_as_float(f2tf32(x)); }
__device__ __forceinline__ void split_tf32(float x, uint32_t& hi, uint32_t& lo) {
    hi = f2tf32(x);
    lo = f2tf32(x - __uint_as_float(hi));
}
__device__ __forceinline__ uint32_t smem_u32(const void* p) {
    uint32_t a;
    asm("{ .reg .u64 t; cvta.to.shared.u64 t, %1; cvt.u32.u64 %0, t; }" : "=r"(a) : "l"(p));
    return a;
}
__device__ __forceinline__ void cpa16(uint32_t dst, const void* src) {
    asm volatile("cp.async.cg.shared.global [%0], [%1], 16;"
                 :: "r"(dst), "l"(__cvta_generic_to_global(src)) : "memory");
}
#define CP_COMMIT() asm volatile("cp.async.commit_group;" ::: "memory")
#define CP_WAIT1()  asm volatile("cp.async.wait_group 1;" ::: "memory")
#define CP_WAIT0()  asm volatile("cp.async.wait_group 0;" ::: "memory")

__device__ __forceinline__ void mma_tf32(float& d0, float& d1, float& d2, float& d3,
                                         uint32_t a0, uint32_t a1, uint32_t a2, uint32_t a3,
                                         uint32_t b0, uint32_t b1) {
    asm volatile(
        "mma.sync.aligned.m16n8k8.row.col.f32.tf32.tf32.f32 "
        "{%0,%1,%2,%3}, {%4,%5,%6,%7}, {%8,%9}, {%0,%1,%2,%3};"
        : "+f"(d0), "+f"(d1), "+f"(d2), "+f"(d3)
        : "r"(a0), "r"(a1), "r"(a2), "r"(a3), "r"(b0), "r"(b1));
}

// ======================= pre-passes =======================
__global__ void k_hid(const float* __restrict__ hid) {
    int i = blockIdx.x * 256 + threadIdx.x;       // float4 index
    float4 v = *(const float4*)(hid + (long)i * 4);
    v.x = rtf(v.x); v.y = rtf(v.y); v.z = rtf(v.z); v.w = rtf(v.w);
    *(float4*)(g_hid32 + (long)i * 4) = v;
}

__global__ void k_tr(const float* __restrict__ q, const float* __restrict__ k,
                     const float* __restrict__ v, const float* __restrict__ p,
                     const float* __restrict__ f1, const float* __restrict__ f2) {
    int i = blockIdx.x * 256 + threadIdx.x;
    if (i < 36864)        g_wtq[(i % 192) * 192 + i / 192] = rtf(q[i]);
    else if (i < 73728)  { int j = i - 36864;  g_wtk[(j % 192) * 192 + j / 192] = rtf(k[j]); }
    else if (i < 110592) { int j = i - 73728;  g_wtv[(j % 192) * 192 + j / 192] = rtf(v[j]); }
    else if (i < 147456) { int j = i - 110592; g_wtp[(j % 192) * 192 + j / 192] = rtf(p[j]); }
    else if (i < 221184) { int j = i - 147456; g_wt1[(j % 384) * 192 + j / 384] = rtf(f1[j]); }
    else if (i < 294912) { int j = i - 221184; g_wt2[(j % 192) * 384 + j / 192] = rtf(f2[j]); }
}

// ======================= CPB / RPB =======================
__device__ __forceinline__ float cpb_coord(float x) {
    x = x / 7.0f * 8.0f;
    float s = (x > 0.f) ? 1.f : ((x < 0.f) ? -1.f : 0.f);
    return s * log2f(fabsf(x) + 1.0f) / log2f(8.0f);
}
__global__ void k_cpb(const float* __restrict__ w1, const float* __restrict__ b1,
                      const float* __restrict__ w2) {
    int row = blockIdx.x;
    int hh = threadIdx.x;
    float t0 = cpb_coord((float)(row / 15) - 7.0f);
    float t1 = cpb_coord((float)(row % 15) - 7.0f);
    float hv = t0 * w1[hh] + t1 * w1[512 + hh] + b1[hh];
    hv = fmaxf(hv, 0.f);
    __shared__ float red[512];
    for (int nh = 0; nh < 6; nh++) {
        red[hh] = hv * w2[hh * 6 + nh];
        __syncthreads();
        for (int s = 256; s > 0; s >>= 1) {
            if (hh < s) red[hh] += red[hh + s];
            __syncthreads();
        }
        if (hh == 0) g_btab[row * 6 + nh] = red[0];
        __syncthreads();
    }
}
__global__ void k_rpb() {
    int idx = blockIdx.x * 256 + threadIdx.x;
    if (idx >= NHEADS * NTOK * NTOK) return;
    int nh = idx >> 12;
    int ij = idx & 4095;
    int i = ij >> 6, j = ij & 63;
    int rel = ((i >> 3) - (j >> 3) + 7) * 15 + ((i & 7) - (j & 7) + 7);
    float b = g_btab[rel * 6 + nh];
    g_rpb[idx] = 16.0f / (1.0f + __expf(-b));
}

// ======================= cp.async tf32 GEMM =======================
#define ACH 4608     // 128*36 floats per A chunk
#define BCH 6912     // 192*36 floats per B buffer

template <int MODE>
__global__ void __launch_bounds__(256, 1) k_g(const float* __restrict__ bias_q,
                                              const float* __restrict__ bias_v) {
    constexpr int NW  = (MODE == 0) ? 3 : ((MODE == 2) ? 2 : 1);
    constexpr int SEQ = NW * 6;
    constexpr int NKB = 12;       // MODE 3 only
    constexpr int WKD = (MODE == 3) ? 384 : 192;   // weight K stride

    extern __shared__ float sm[];
    float* smA = sm;
    float* smB = sm + ((MODE == 3) ? 2 * ACH : 6 * ACH);
    uint32_t sbA = smem_u32(smA), sbB = smem_u32(smB);

    int tid = threadIdx.x;
    int wid = tid >> 5, lane = tid & 31;
    int qr = lane >> 2, qc = lane & 3;
    int tile = blockIdx.x;
    int rb = (wid & 1) * 64;
    int nb0 = (wid >> 1) * 48;

    const float* Asrc;
    if (MODE == 0) Asrc = g_hid32;
    else if (MODE == 1) Asrc = g_ctx;
    else if (MODE == 2) Asrc = g_h32;
    else Asrc = g_mid;

    auto a_src = [&](int row, int kb) -> const float* {
        long tau = (long)tile * 128 + row;
        if (MODE == 0) {
            int win = (int)(tau >> 6), n = (int)(tau & 63);
            int r0 = (win / 48) * 8 + (n >> 3) + SHIFTV; if (r0 >= HH) r0 -= HH;
            int c0 = (win % 48) * 8 + (n & 7)  + SHIFTV; if (c0 >= HH) c0 -= HH;
            return Asrc + (long)(r0 * HH + c0) * CC + kb * 32;
        }
        return Asrc + tau * ((MODE == 3) ? 384 : 192) + kb * 32;
    };

    auto issue_B = [&](const float* Wt, int nrow_base, int kb, int buf) {
#pragma unroll
        for (int i = 0; i < 6; i++) {
            int idx = tid + i * 256;
            int row = idx >> 3, kc = idx & 7;
            cpa16(sbB + (uint32_t)(buf * BCH + row * 36 + kc * 4) * 4,
                  Wt + (long)(nrow_base + row) * WKD + kb * 32 + kc * 4);
        }
    };
    auto issue_A_chunk = [&](int kb, int buf) {
#pragma unroll
        for (int i = 0; i < 4; i++) {
            int idx = tid + i * 256;
            int row = idx >> 3, kc = idx & 7;
            cpa16(sbA + (uint32_t)(buf * ACH + row * 36 + kc * 4) * 4,
                  a_src(row, kb) + kc * 4);
        }
    };

    float acc[4][6][4];
#pragma unroll
    for (int mf = 0; mf < 4; mf++)
#pragma unroll
        for (int nf = 0; nf < 6; nf++)
#pragma unroll
            for (int t = 0; t < 4; t++) acc[mf][nf][t] = 0.f;

    auto do_mma = [&](const uint32_t* A, const uint32_t* B) {
#pragma unroll
        for (int k8 = 0; k8 < 4; k8++) {
            int kof = k8 * 8;
            uint32_t a[4][4];
#pragma unroll
            for (int mf = 0; mf < 4; mf++) {
                int r = rb + mf * 16 + qr;
                a[mf][0] = A[r * 36 + kof + qc];
                a[mf][1] = A[(r + 8) * 36 + kof + qc];
                a[mf][2] = A[r * 36 + kof + qc + 4];
                a[mf][3] = A[(r + 8) * 36 + kof + qc + 4];
            }
#pragma unroll
            for (int nf = 0; nf < 6; nf++) {
                int n = nb0 + nf * 8 + qr;
                uint32_t b0 = B[n * 36 + kof + qc];
                uint32_t b1 = B[n * 36 + kof + qc + 4];
#pragma unroll
                for (int mf = 0; mf < 4; mf++)
                    mma_tf32(acc[mf][nf][0], acc[mf][nf][1], acc[mf][nf][2], acc[mf][nf][3],
                             a[mf][0], a[mf][1], a[mf][2], a[mf][3], b0, b1);
            }
        }
    };

    auto epilogue = [&](int w) {
        const float* bias;
        if (MODE == 0)      bias = (w == 0) ? bias_q : ((w == 1) ? nullptr : bias_v);
        else                bias = bias_q;
#pragma unroll
        for (int mf = 0; mf < 4; mf++) {
#pragma unroll
            for (int t = 0; t < 2; t++) {
                int rloc = rb + mf * 16 + qr + t * 8;
                long tau = (long)tile * 128 + rloc;
                int win = (int)(tau >> 6), n = (int)(tau & 63);
#pragma unroll
                for (int nf = 0; nf < 6; nf++) {
                    int cloc = nb0 + nf * 8 + qc * 2;
                    float vx = acc[mf][nf][t * 2 + 0];
                    float vy = acc[mf][nf][t * 2 + 1];
                    if (MODE == 0) {
                        if (bias) { vx += bias[cloc]; vy += bias[cloc + 1]; }
                        int head = cloc >> 5, d = cloc & 31;
                        float* dst = ((w == 0) ? g_q : ((w == 1) ? g_k : g_v)) +
                                     (((long)(win * 6 + head) * 64 + n) << 5) + d;
                        *(float2*)dst = make_float2(vx, vy);
                    } else if (MODE == 1) {
                        vx += bias[cloc]; vy += bias[cloc + 1];
                        int r0 = (win / 48) * 8 + (n >> 3) + SHIFTV; if (r0 >= HH) r0 -= HH;
                        int c0 = (win % 48) * 8 + (n & 7)  + SHIFTV; if (c0 >= HH) c0 -= HH;
                        float* dst = g_xattn + (long)(r0 * HH + c0) * CC + cloc;
                        *(float2*)dst = make_float2(vx, vy);
                    } else if (MODE == 2) {
                        int col = w * 192 + cloc;
                        vx += bias[col]; vy += bias[col + 1];
                        vx = 0.5f * vx * (1.0f + erff(vx * 0.70710678118654752f));
                        vy = 0.5f * vy * (1.0f + erff(vy * 0.70710678118654752f));
                        float* dst = g_mid + tau * 384 + col;
                        *(float2*)dst = make_float2(rtf(vx), rtf(vy));
                    } else {
                        vx += bias[cloc]; vy += bias[cloc + 1];
                        float* dst = g_mlp + tau * CC + cloc;
                        *(float2*)dst = make_float2(vx, vy);
                    }
                }
            }
        }
        if (MODE == 0 || MODE == 2) {
#pragma unroll
            for (int mf = 0; mf < 4; mf++)
#pragma unroll
                for (int nf = 0; nf < 6; nf++)
#pragma unroll
                    for (int t = 0; t < 4; t++) acc[mf][nf][t] = 0.f;
        }
    };

    if (MODE != 3) {
        // A resident: all 6 chunks + B0 in group0, B1 in group1
#pragma unroll
        for (int i = 0; i < 24; i++) {
            int idx = tid + i * 256;
            int ch = idx >> 10, t = idx & 1023;
            int row = t >> 3, kc = t & 7;
            cpa16(sbA + (uint32_t)(ch * ACH + row * 36 + kc * 4) * 4,
                  a_src(row, ch) + kc * 4);
        }
        const float* W0 = (MODE == 0) ? g_wtq : ((MODE == 1) ? g_wtp : g_wt1);
        issue_B(W0, 0, 0, 0);
        CP_COMMIT();
        issue_B(W0, 0, 1, 1);
        CP_COMMIT();

        for (int s = 0; s < SEQ; s++) {
            int w = s / 6, kb = s % 6, buf = s & 1;
            if (s >= SEQ - 1) { CP_WAIT0(); } else { CP_WAIT1(); }
            __syncthreads();
            do_mma((const uint32_t*)(smA + kb * ACH), (const uint32_t*)(smB + buf * BCH));
            if (kb == 5) epilogue(w);
            __syncthreads();
            int s2 = s + 2;
            if (s2 < SEQ) {
                int w2 = s2 / 6, kb2 = s2 % 6;
                const float* Wt;
                int nrb = 0;
                if (MODE == 0)      Wt = (w2 == 0) ? g_wtq : ((w2 == 1) ? g_wtk : g_wtv);
                else if (MODE == 1) Wt = g_wtp;
                else                { Wt = g_wt1; nrb = w2 * 192; }
                issue_B(Wt, nrb, kb2, s2 & 1);
                CP_COMMIT();
            }
        }
    } else {
        issue_A_chunk(0, 0); issue_B(g_wt2, 0, 0, 0);
        CP_COMMIT();
        issue_A_chunk(1, 1); issue_B(g_wt2, 0, 1, 1);
        CP_COMMIT();
        for (int s = 0; s < NKB; s++) {
            int buf = s & 1;
            if (s >= NKB - 1) { CP_WAIT0(); } else { CP_WAIT1(); }
            __syncthreads();
            do_mma((const uint32_t*)(smA + buf * ACH), (const uint32_t*)(smB + buf * BCH));
            __syncthreads();
            int s2 = s + 2;
            if (s2 < NKB) {
                issue_A_chunk(s2, s2 & 1);
                issue_B(g_wt2, 0, s2, s2 & 1);
                CP_COMMIT();
            }
        }
        epilogue(0);
    }
}

// ======================= tensor-core attention (split tf32) =======================
__global__ void __launch_bounds__(128) k_attn(const float* __restrict__ logit_scale) {
    __shared__ float qs[64][36], ks[64][36], vs[64][36];
    __shared__ float ps[64][68];
    __shared__ float qinv[64], kinv[64];
    __shared__ int lab[64];
    __shared__ float sscale;

    int w = blockIdx.x, hd = blockIdx.y;
    int tid = threadIdx.x;
    int wid = tid >> 5, lane = tid & 31;
    int qr = lane >> 2, qc = lane & 3;
    int m0 = wid * 16;

    long base = ((long)(w * 6 + hd) * 64) * 32;
#pragma unroll
    for (int it = 0; it < 4; it++) {
        int s = tid + it * 128;
        int n = s >> 3, c4 = s & 7;
        *(float4*)&qs[n][c4 * 4] = *(const float4*)(g_q + base + n * 32 + c4 * 4);
        *(float4*)&ks[n][c4 * 4] = *(const float4*)(g_k + base + n * 32 + c4 * 4);
        *(float4*)&vs[n][c4 * 4] = *(const float4*)(g_v + base + n * 32 + c4 * 4);
    }
    if (tid == 0) sscale = __expf(fminf(logit_scale[hd], logf(100.f)));
    __syncthreads();

    if (tid < 64) {
        float s2 = 0.f;
#pragma unroll
        for (int d = 0; d < 32; d++) s2 += qs[tid][d] * qs[tid][d];
        qinv[tid] = 1.f / fmaxf(sqrtf(s2), 1e-12f);
        int r = (w / 48) * 8 + (tid >> 3);
        int c = (w % 48) * 8 + (tid & 7);
        int rr = (r < HH - WSZ) ? 0 : ((r < HH - SHIFTV) ? 1 : 2);
        int rc = (c < HH - WSZ) ? 0 : ((c < HH - SHIFTV) ? 1 : 2);
        lab[tid] = rr * 3 + rc;
    } else {
        int n = tid - 64;
        float s2 = 0.f;
#pragma unroll
        for (int d = 0; d < 32; d++) s2 += ks[n][d] * ks[n][d];
        kinv[n] = 1.f / fmaxf(sqrtf(s2), 1e-12f);
    }
    __syncthreads();

    float acc[8][4];
#pragma unroll
    for (int nt = 0; nt < 8; nt++)
#pragma unroll
        for (int t = 0; t < 4; t++) acc[nt][t] = 0.f;

    int i0 = m0 + qr, i1 = m0 + qr + 8;
    float qi0 = qinv[i0], qi1 = qinv[i1];

#pragma unroll
    for (int kt = 0; kt < 4; kt++) {
        int k0 = kt * 8;
        uint32_t ah[4], al[4];
        split_tf32(qs[i0][k0 + qc] * qi0,     ah[0], al[0]);
        split_tf32(qs[i1][k0 + qc] * qi1,     ah[1], al[1]);
        split_tf32(qs[i0][k0 + qc + 4] * qi0, ah[2], al[2]);
        split_tf32(qs[i1][k0 + qc + 4] * qi1, ah[3], al[3]);
#pragma unroll
        for (int nt = 0; nt < 8; nt++) {
            int j = nt * 8 + qr;
            float ki = kinv[j];
            uint32_t bh0, bl0, bh1, bl1;
            split_tf32(ks[j][k0 + qc] * ki,     bh0, bl0);
            split_tf32(ks[j][k0 + qc + 4] * ki, bh1, bl1);
            mma_tf32(acc[nt][0], acc[nt][1], acc[nt][2], acc[nt][3],
                     ah[0], ah[1], ah[2], ah[3], bh0, bh1);
            mma_tf32(acc[nt][0], acc[nt][1], acc[nt][2], acc[nt][3],
                     ah[0], ah[1], ah[2], ah[3], bl0, bl1);
            mma_tf32(acc[nt][0], acc[nt][1], acc[nt][2], acc[nt][3],
                     al[0], al[1], al[2], al[3], bh0, bh1);
        }
    }

    float scl = sscale;
    int labi0 = lab[i0], labi1 = lab[i1];
    const float* rpb = g_rpb + (hd << 12);
    float mx0 = -1e30f, mx1 = -1e30f;
#pragma unroll
    for (int nt = 0; nt < 8; nt++) {
#pragma unroll
        for (int e = 0; e < 2; e++) {
            int j = nt * 8 + 2 * qc + e;
            int labj = lab[j];
            float s0 = acc[nt][e] * scl + rpb[(i0 << 6) + j];
            if (labi0 != labj) s0 -= 200.f;
            float s1 = acc[nt][2 + e] * scl + rpb[(i1 << 6) + j];
            if (labi1 != labj) s1 -= 200.f;
            acc[nt][e] = s0; acc[nt][2 + e] = s1;
            mx0 = fmaxf(mx0, s0); mx1 = fmaxf(mx1, s1);
        }
    }
    mx0 = fmaxf(mx0, __shfl_xor_sync(0xffffffffu, mx0, 1));
    mx0 = fmaxf(mx0, __shfl_xor_sync(0xffffffffu, mx0, 2));
    mx1 = fmaxf(mx1, __shfl_xor_sync(0xffffffffu, mx1, 1));
    mx1 = fmaxf(mx1, __shfl_xor_sync(0xffffffffu, mx1, 2));
    float sum0 = 0.f, sum1 = 0.f;
#pragma unroll
    for (int nt = 0; nt < 8; nt++) {
#pragma unroll
        for (int e = 0; e < 2; e++) {
            float e0 = __expf(acc[nt][e] - mx0);
            float e1 = __expf(acc[nt][2 + e] - mx1);
            acc[nt][e] = e0; acc[nt][2 + e] = e1;
            sum0 += e0; sum1 += e1;
        }
    }
    sum0 += __shfl_xor_sync(0xffffffffu, sum0, 1);
    sum0 += __shfl_xor_sync(0xffffffffu, sum0, 2);
    sum1 += __shfl_xor_sync(0xffffffffu, sum1, 1);
    sum1 += __shfl_xor_sync(0xffffffffu, sum1, 2);
    float r0 = 1.f / sum0, r1 = 1.f / sum1;
#pragma unroll
    for (int nt = 0; nt < 8; nt++) {
        int j = nt * 8 + 2 * qc;
        ps[i0][j]     = acc[nt][0] * r0;
        ps[i0][j + 1] = acc[nt][1] * r0;
        ps[i1][j]     = acc[nt][2] * r1;
        ps[i1][j + 1] = acc[nt][3] * r1;
    }
    __syncwarp();

    float o[4][4];
#pragma unroll
    for (int nt = 0; nt < 4; nt++)
#pragma unroll
        for (int t = 0; t < 4; t++) o[nt][t] = 0.f;

#pragma unroll
    for (int kt = 0; kt < 8; kt++) {
        int k0 = kt * 8;
        uint32_t ah[4], al[4];
        split_tf32(ps[i0][k0 + qc],     ah[0], al[0]);
        split_tf32(ps[i1][k0 + qc],     ah[1], al[1]);
        split_tf32(ps[i0][k0 + qc + 4], ah[2], al[2]);
        split_tf32(ps[i1][k0 + qc + 4], ah[3], al[3]);
#pragma unroll
        for (int nt = 0; nt < 4; nt++) {
            int d = nt * 8 + qr;
            uint32_t bh0, bl0, bh1, bl1;
            split_tf32(vs[k0 + qc][d],     bh0, bl0);
            split_tf32(vs[k0 + qc + 4][d], bh1, bl1);
            mma_tf32(o[nt][0], o[nt][1], o[nt][2], o[nt][3],
                     ah[0], ah[1], ah[2], ah[3], bh0, bh1);
            mma_tf32(o[nt][0], o[nt][1], o[nt][2], o[nt][3],
                     ah[0], ah[1], ah[2], ah[3], bl0, bl1);
            mma_tf32(o[nt][0], o[nt][1], o[nt][2], o[nt][3],
                     al[0], al[1], al[2], al[3], bh0, bh1);
        }
    }

    float* ob0 = g_ctx + ((long)(w * 64 + i0)) * CC + (hd << 5);
    float* ob1 = g_ctx + ((long)(w * 64 + i1)) * CC + (hd << 5);
#pragma unroll
    for (int nt = 0; nt < 4; nt++) {
        int d = nt * 8 + 2 * qc;
        *(float2*)(ob0 + d) = make_float2(rtf(o[nt][0]), rtf(o[nt][1]));
        *(float2*)(ob1 + d) = make_float2(rtf(o[nt][2]), rtf(o[nt][3]));
    }
}

// ======================= LayerNorm + residual =======================
__global__ void __launch_bounds__(256) k_ln_add(
    const float* __restrict__ xres, const float* __restrict__ xln,
    const float* __restrict__ g, const float* __restrict__ b,
    float* __restrict__ out, float* __restrict__ out32) {
    int t = blockIdx.x * 8 + (threadIdx.x >> 5);
    int lane = threadIdx.x & 31;
    const float* row = xln + t * CC;
    float v[6];
    float sum = 0.f;
#pragma unroll
    for (int i = 0; i < 6; i++) { v[i] = row[lane + 32 * i]; sum += v[i]; }
#pragma unroll
    for (int o = 16; o > 0; o >>= 1) sum += __shfl_xor_sync(0xffffffffu, sum, o);
    float mu = sum * (1.0f / CC);
    float vs = 0.f;
#pragma unroll
    for (int i = 0; i < 6; i++) { float d = v[i] - mu; vs += d * d; }
#pragma unroll
    for (int o = 16; o > 0; o >>= 1) vs += __shfl_xor_sync(0xffffffffu, vs, o);
    float inv = rsqrtf(vs * (1.0f / CC) + 1e-5f);
#pragma unroll
    for (int i = 0; i < 6; i++) {
        int ch = lane + 32 * i;
        float r = xres[t * CC + ch] + (v[i] - mu) * inv * g[ch] + b[ch];
        out[t * CC + ch] = r;
        if (out32) out32[t * CC + ch] = rtf(r);
    }
}

// ======================= launch =======================
extern "C" void kernel_launch(void* const* d_in, const int* in_sizes, int n_in,
                              void* d_out, int out_size) {
    const float* hidden = (const float*)d_in[0];
    const float* q_w    = (const float*)d_in[1];
    const float* q_b    = (const float*)d_in[2];
    const float* k_w    = (const float*)d_in[3];
    const float* v_w    = (const float*)d_in[4];
    const float* v_b    = (const float*)d_in[5];
    const float* lscale = (const float*)d_in[6];
    const float* cpb_w1 = (const float*)d_in[7];
    const float* cpb_b1 = (const float*)d_in[8];
    const float* cpb_w2 = (const float*)d_in[9];
    const float* proj_w = (const float*)d_in[10];
    const float* proj_b = (const float*)d_in[11];
    const float* ln1_g  = (const float*)d_in[12];
    const float* ln1_b  = (const float*)d_in[13];
    const float* fc1_w  = (const float*)d_in[14];
    const float* fc1_b  = (const float*)d_in[15];
    const float* fc2_w  = (const float*)d_in[16];
    const float* fc2_b  = (const float*)d_in[17];
    const float* ln2_g  = (const float*)d_in[18];
    const float* ln2_b  = (const float*)d_in[19];
    float* out = (float*)d_out;

    float* gh; float* gxa; float* gmlp; float* gh32;
    cudaGetSymbolAddress((void**)&gh, g_h);
    cudaGetSymbolAddress((void**)&gxa, g_xattn);
    cudaGetSymbolAddress((void**)&gmlp, g_mlp);
    cudaGetSymbolAddress((void**)&gh32, g_h32);

    const int SM_RES = (6 * ACH + 2 * BCH) * 4;   // 165,888 B
    const int SM_STR = (2 * ACH + 2 * BCH) * 4;   //  92,160 B
    cudaFuncSetAttribute(k_g<0>, cudaFuncAttributeMaxDynamicSharedMemorySize, SM_RES);
    cudaFuncSetAttribute(k_g<1>, cudaFuncAttributeMaxDynamicSharedMemorySize, SM_RES);
    cudaFuncSetAttribute(k_g<2>, cudaFuncAttributeMaxDynamicSharedMemorySize, SM_RES);
    cudaFuncSetAttribute(k_g<3>, cudaFuncAttributeMaxDynamicSharedMemorySize, SM_STR);

    k_tr<<<1152, 256>>>(q_w, k_w, v_w, proj_w, fc1_w, fc2_w);
    k_hid<<<TT * CC / 4 / 256, 256>>>(hidden);
    k_cpb<<<225, 512>>>(cpb_w1, cpb_b1, cpb_w2);
    k_rpb<<<(NHEADS * NTOK * NTOK + 255) / 256, 256>>>();
    k_g<0><<<1152, 256, SM_RES>>>(q_b, v_b);
    k_attn<<<dim3(NWIN, NHEADS), 128>>>(lscale);
    k_g<1><<<1152, 256, SM_RES>>>(proj_b, nullptr);
    k_ln_add<<<TT / 8, 256>>>(hidden, gxa, ln1_g, ln1_b, gh, gh32);
    k_g<2><<<1152, 256, SM_RES>>>(fc1_b, nullptr);
    k_g<3><<<1152, 256, SM_STR>>>(fc2_b, nullptr);
    k_ln_add<<<TT / 8, 256>>>(gh, gmlp, ln2_g, ln2_b, out, nullptr);
}

// round 8
// speedup vs baseline: 1.0161x; 1.0161x over previous
#include <cuda_runtime.h>
#include <math.h>
#include <cstdint>

#define HH 384
#define CC 192
#define WSZ 8
#define SHIFTV 4
#define NHEADS 6
#define HDIM 32
#define NTOK 64
#define NWIN 2304
#define TT 147456

// -------- scratch (device globals) --------
__device__ float g_q[NWIN*NHEADS*NTOK*HDIM];
__device__ float g_k[NWIN*NHEADS*NTOK*HDIM];
__device__ float g_v[NWIN*NHEADS*NTOK*HDIM];
__device__ float g_ctx[TT*CC];
__device__ float g_xattn[TT*CC];
__device__ float g_h[TT*CC];
__device__ float g_mid[TT*2*CC];
__device__ float g_mlp[TT*CC];
__device__ float g_rpb[NHEADS*NTOK*NTOK];
__device__ float g_btab[225*NHEADS];
// transposed weights [N, K] K-major
__device__ float g_wtq[CC*CC];
__device__ float g_wtk[CC*CC];
__device__ float g_wtv[CC*CC];
__device__ float g_wtp[CC*CC];
__device__ float g_wt1[2*CC*CC];   // [384, 192]
__device__ float g_wt2[CC*2*CC];   // [192, 384]

__device__ __forceinline__ uint32_t f2tf32(float x) {
    uint32_t r;
    asm("cvt.rna.tf32.f32 %0, %1;" : "=r"(r) : "f"(x));
    return r;
}
__device__ __forceinline__ void split_tf32(float x, uint32_t& hi, uint32_t& lo) {
    hi = f2tf32(x);
    lo = f2tf32(x - __uint_as_float(hi));
}

__device__ __forceinline__ void mma_tf32(float& d0, float& d1, float& d2, float& d3,
                                         uint32_t a0, uint32_t a1, uint32_t a2, uint32_t a3,
                                         uint32_t b0, uint32_t b1) {
    asm volatile(
        "mma.sync.aligned.m16n8k8.row.col.f32.tf32.tf32.f32 "
        "{%0,%1,%2,%3}, {%4,%5,%6,%7}, {%8,%9}, {%0,%1,%2,%3};"
        : "+f"(d0), "+f"(d1), "+f"(d2), "+f"(d3)
        : "r"(a0), "r"(a1), "r"(a2), "r"(a3), "r"(b0), "r"(b1));
}

// ======================= weight transpose =======================
__global__ void k_tr(const float* __restrict__ q, const float* __restrict__ k,
                     const float* __restrict__ v, const float* __restrict__ p,
                     const float* __restrict__ f1, const float* __restrict__ f2) {
    int i = blockIdx.x * 256 + threadIdx.x;
    if (i < 36864)        g_wtq[(i % 192) * 192 + i / 192] = q[i];
    else if (i < 73728)  { int j = i - 36864;  g_wtk[(j % 192) * 192 + j / 192] = k[j]; }
    else if (i < 110592) { int j = i - 73728;  g_wtv[(j % 192) * 192 + j / 192] = v[j]; }
    else if (i < 147456) { int j = i - 110592; g_wtp[(j % 192) * 192 + j / 192] = p[j]; }
    else if (i < 221184) { int j = i - 147456; g_wt1[(j % 384) * 192 + j / 384] = f1[j]; }
    else if (i < 294912) { int j = i - 221184; g_wt2[(j % 192) * 384 + j / 192] = f2[j]; }
}

// ======================= CPB / RPB =======================
__device__ __forceinline__ float cpb_coord(float x) {
    x = x / 7.0f * 8.0f;
    float s = (x > 0.f) ? 1.f : ((x < 0.f) ? -1.f : 0.f);
    return s * log2f(fabsf(x) + 1.0f) / log2f(8.0f);
}
__global__ void k_cpb(const float* __restrict__ w1, const float* __restrict__ b1,
                      const float* __restrict__ w2) {
    int row = blockIdx.x;
    int hh = threadIdx.x;
    float t0 = cpb_coord((float)(row / 15) - 7.0f);
    float t1 = cpb_coord((float)(row % 15) - 7.0f);
    float hv = t0 * w1[hh] + t1 * w1[512 + hh] + b1[hh];
    hv = fmaxf(hv, 0.f);
    __shared__ float red[512];
    for (int nh = 0; nh < 6; nh++) {
        red[hh] = hv * w2[hh * 6 + nh];
        __syncthreads();
        for (int s = 256; s > 0; s >>= 1) {
            if (hh < s) red[hh] += red[hh + s];
            __syncthreads();
        }
        if (hh == 0) g_btab[row * 6 + nh] = red[0];
        __syncthreads();
    }
}
__global__ void k_rpb() {
    int idx = blockIdx.x * 256 + threadIdx.x;
    if (idx >= NHEADS * NTOK * NTOK) return;
    int nh = idx >> 12;
    int ij = idx & 4095;
    int i = ij >> 6, j = ij & 63;
    int rel = ((i >> 3) - (j >> 3) + 7) * 15 + ((i & 7) - (j & 7) + 7);
    float b = g_btab[rel * 6 + nh];
    g_rpb[idx] = 16.0f / (1.0f + __expf(-b));
}

// ======================= tf32 mma.sync GEMM (512 threads, 16 warps 4x4) =======================
// Block tile 128(M) x 192(N); warp tile 32x48 (2 mf x 6 nf).
// MODE 0: QKV  grid(1152, 3=weight)  A gathered from hidden
// MODE 1: proj grid(1152, 1)         A=g_ctx, scatter out
// MODE 2: fc1  grid(1152, 2=N half)  A=g_h, gelu
// MODE 3: fc2  grid(1152, 1)         A=g_mid (K=384)
#define SA_ROW 36
#define OFF_A0 0
#define OFF_A1 (128*SA_ROW)
#define OFF_B0 (2*128*SA_ROW)
#define OFF_B1 (2*128*SA_ROW + 192*SA_ROW)
#define SMEM_FLOATS (2*128*SA_ROW + 2*192*SA_ROW)

template <int MODE>
__global__ void __launch_bounds__(512, 1) k_g(const float* __restrict__ Xin,
                                              const float* __restrict__ bias_q,
                                              const float* __restrict__ bias_v) {
    constexpr int KD  = (MODE == 3) ? 384 : 192;
    constexpr int NKB = KD / 32;

    extern __shared__ float sm[];
    int tid = threadIdx.x;
    int wid = tid >> 5, lane = tid & 31;
    int qr = lane >> 2, qc = lane & 3;
    int tile = blockIdx.x;
    int yb = blockIdx.y;

    const float* Wt;
    const float* bias;
    if (MODE == 0) {
        Wt = (yb == 0) ? g_wtq : ((yb == 1) ? g_wtk : g_wtv);
        bias = (yb == 0) ? bias_q : ((yb == 1) ? nullptr : bias_v);
    } else if (MODE == 1) { Wt = g_wtp; bias = bias_q; }
    else if (MODE == 2)   { Wt = g_wt1; bias = bias_q; }
    else                  { Wt = g_wt2; bias = bias_q; }
    int nrow_base = (MODE == 2) ? yb * 192 : 0;

    const float* Asrc;
    if (MODE == 0) Asrc = Xin;
    else if (MODE == 1) Asrc = g_ctx;
    else if (MODE == 2) Asrc = g_h;
    else Asrc = g_mid;

    float4 ar[2];
    float4 br[3];

    auto a_ptr = [&](int row, int kb, int kc) -> const float* {
        long tau = (long)tile * 128 + row;
        if (MODE == 0) {
            int win = (int)(tau >> 6), n = (int)(tau & 63);
            int r0 = (win / 48) * 8 + (n >> 3) + SHIFTV; if (r0 >= HH) r0 -= HH;
            int c0 = (win % 48) * 8 + (n & 7)  + SHIFTV; if (c0 >= HH) c0 -= HH;
            return Asrc + (long)(r0 * HH + c0) * CC + kb * 32 + kc * 4;
        }
        return Asrc + tau * KD + kb * 32 + kc * 4;
    };

    auto LOADREG = [&](int kb) {
#pragma unroll
        for (int i = 0; i < 2; i++) {
            int idx = tid + i * 512;
            int row = idx >> 3, kc = idx & 7;
            ar[i] = *(const float4*)a_ptr(row, kb, kc);
        }
#pragma unroll
        for (int i = 0; i < 3; i++) {
            int idx = tid + i * 512;
            int row = idx >> 3, kc = idx & 7;
            br[i] = *(const float4*)(Wt + (long)(nrow_base + row) * KD + kb * 32 + kc * 4);
        }
    };
    auto STORE = [&](int stg) {
        float* A = sm + (stg ? OFF_A1 : OFF_A0);
        float* B = sm + (stg ? OFF_B1 : OFF_B0);
#pragma unroll
        for (int i = 0; i < 2; i++) {
            int idx = tid + i * 512;
            int row = idx >> 3, kc = idx & 7;
            float* d = A + row * SA_ROW + kc * 4;
            d[0] = __uint_as_float(f2tf32(ar[i].x));
            d[1] = __uint_as_float(f2tf32(ar[i].y));
            d[2] = __uint_as_float(f2tf32(ar[i].z));
            d[3] = __uint_as_float(f2tf32(ar[i].w));
        }
#pragma unroll
        for (int i = 0; i < 3; i++) {
            int idx = tid + i * 512;
            int row = idx >> 3, kc = idx & 7;
            float* d = B + row * SA_ROW + kc * 4;
            d[0] = __uint_as_float(f2tf32(br[i].x));
            d[1] = __uint_as_float(f2tf32(br[i].y));
            d[2] = __uint_as_float(f2tf32(br[i].z));
            d[3] = __uint_as_float(f2tf32(br[i].w));
        }
    };

    float acc[2][6][4];
#pragma unroll
    for (int mf = 0; mf < 2; mf++)
#pragma unroll
        for (int nf = 0; nf < 6; nf++)
#pragma unroll
            for (int t = 0; t < 4; t++) acc[mf][nf][t] = 0.f;

    int rb = (wid & 3) * 32;
    int nb0 = (wid >> 2) * 48;

    LOADREG(0);
    STORE(0);
    for (int kb = 0; kb < NKB; kb++) {
        if (kb + 1 < NKB) LOADREG(kb + 1);
        __syncthreads();
        const uint32_t* A = (const uint32_t*)(sm + ((kb & 1) ? OFF_A1 : OFF_A0));
        const uint32_t* B = (const uint32_t*)(sm + ((kb & 1) ? OFF_B1 : OFF_B0));
#pragma unroll
        for (int k8 = 0; k8 < 4; k8++) {
            int kof = k8 * 8;
            uint32_t a[2][4];
#pragma unroll
            for (int mf = 0; mf < 2; mf++) {
                int r = rb + mf * 16 + qr;
                a[mf][0] = A[r * SA_ROW + kof + qc];
                a[mf][1] = A[(r + 8) * SA_ROW + kof + qc];
                a[mf][2] = A[r * SA_ROW + kof + qc + 4];
                a[mf][3] = A[(r + 8) * SA_ROW + kof + qc + 4];
            }
#pragma unroll
            for (int nf = 0; nf < 6; nf++) {
                int n = nb0 + nf * 8 + qr;
                uint32_t b0 = B[n * SA_ROW + kof + qc];
                uint32_t b1 = B[n * SA_ROW + kof + qc + 4];
#pragma unroll
                for (int mf = 0; mf < 2; mf++)
                    mma_tf32(acc[mf][nf][0], acc[mf][nf][1], acc[mf][nf][2], acc[mf][nf][3],
                             a[mf][0], a[mf][1], a[mf][2], a[mf][3], b0, b1);
            }
        }
        if (kb + 1 < NKB) STORE((kb + 1) & 1);
    }

    // ---- epilogue ----
#pragma unroll
    for (int mf = 0; mf < 2; mf++) {
#pragma unroll
        for (int t = 0; t < 2; t++) {
            int rloc = rb + mf * 16 + qr + t * 8;
            long tau = (long)tile * 128 + rloc;
            int win = (int)(tau >> 6), n = (int)(tau & 63);
#pragma unroll
            for (int nf = 0; nf < 6; nf++) {
                int cloc = nb0 + nf * 8 + qc * 2;
                float vx = acc[mf][nf][t * 2 + 0];
                float vy = acc[mf][nf][t * 2 + 1];
                if (MODE == 0) {
                    if (bias) { vx += bias[cloc]; vy += bias[cloc + 1]; }
                    int head = cloc >> 5, d = cloc & 31;
                    float* dst = ((yb == 0) ? g_q : ((yb == 1) ? g_k : g_v)) +
                                 (((long)(win * 6 + head) * 64 + n) << 5) + d;
                    *(float2*)dst = make_float2(vx, vy);
                } else if (MODE == 1) {
                    vx += bias[cloc]; vy += bias[cloc + 1];
                    int r0 = (win / 48) * 8 + (n >> 3) + SHIFTV; if (r0 >= HH) r0 -= HH;
                    int c0 = (win % 48) * 8 + (n & 7)  + SHIFTV; if (c0 >= HH) c0 -= HH;
                    float* dst = g_xattn + (long)(r0 * HH + c0) * CC + cloc;
                    *(float2*)dst = make_float2(vx, vy);
                } else if (MODE == 2) {
                    int col = yb * 192 + cloc;
                    vx += bias[col]; vy += bias[col + 1];
                    vx = 0.5f * vx * (1.0f + erff(vx * 0.70710678118654752f));
                    vy = 0.5f * vy * (1.0f + erff(vy * 0.70710678118654752f));
                    float* dst = g_mid + tau * 384 + col;
                    *(float2*)dst = make_float2(vx, vy);
                } else {
                    vx += bias[cloc]; vy += bias[cloc + 1];
                    float* dst = g_mlp + tau * CC + cloc;
                    *(float2*)dst = make_float2(vx, vy);
                }
            }
        }
    }
}

// ======================= tensor-core attention (split tf32) =======================
__global__ void __launch_bounds__(128) k_attn(const float* __restrict__ logit_scale) {
    __shared__ float qs[64][36], ks[64][36], vs[64][36];
    __shared__ float ps[64][68];
    __shared__ float qinv[64], kinv[64];
    __shared__ int lab[64];
    __shared__ float sscale;

    int w = blockIdx.x, hd = blockIdx.y;
    int tid = threadIdx.x;
    int wid = tid >> 5, lane = tid & 31;
    int qr = lane >> 2, qc = lane & 3;
    int m0 = wid * 16;

    long base = ((long)(w * 6 + hd) * 64) * 32;
#pragma unroll
    for (int it = 0; it < 4; it++) {
        int s = tid + it * 128;
        int n = s >> 3, c4 = s & 7;
        *(float4*)&qs[n][c4 * 4] = *(const float4*)(g_q + base + n * 32 + c4 * 4);
        *(float4*)&ks[n][c4 * 4] = *(const float4*)(g_k + base + n * 32 + c4 * 4);
        *(float4*)&vs[n][c4 * 4] = *(const float4*)(g_v + base + n * 32 + c4 * 4);
    }
    if (tid == 0) sscale = __expf(fminf(logit_scale[hd], logf(100.f)));
    __syncthreads();

    if (tid < 64) {
        float s2 = 0.f;
#pragma unroll
        for (int d = 0; d < 32; d++) s2 += qs[tid][d] * qs[tid][d];
        qinv[tid] = 1.f / fmaxf(sqrtf(s2), 1e-12f);
        int r = (w / 48) * 8 + (tid >> 3);
        int c = (w % 48) * 8 + (tid & 7);
        int rr = (r < HH - WSZ) ? 0 : ((r < HH - SHIFTV) ? 1 : 2);
        int rc = (c < HH - WSZ) ? 0 : ((c < HH - SHIFTV) ? 1 : 2);
        lab[tid] = rr * 3 + rc;
    } else {
        int n = tid - 64;
        float s2 = 0.f;
#pragma unroll
        for (int d = 0; d < 32; d++) s2 += ks[n][d] * ks[n][d];
        kinv[n] = 1.f / fmaxf(sqrtf(s2), 1e-12f);
    }
    __syncthreads();

    float acc[8][4];
#pragma unroll
    for (int nt = 0; nt < 8; nt++)
#pragma unroll
        for (int t = 0; t < 4; t++) acc[nt][t] = 0.f;

    int i0 = m0 + qr, i1 = m0 + qr + 8;
    float qi0 = qinv[i0], qi1 = qinv[i1];

#pragma unroll
    for (int kt = 0; kt < 4; kt++) {
        int k0 = kt * 8;
        uint32_t ah[4], al[4];
        split_tf32(qs[i0][k0 + qc] * qi0,     ah[0], al[0]);
        split_tf32(qs[i1][k0 + qc] * qi1,     ah[1], al[1]);
        split_tf32(qs[i0][k0 + qc + 4] * qi0, ah[2], al[2]);
        split_tf32(qs[i1][k0 + qc + 4] * qi1, ah[3], al[3]);
#pragma unroll
        for (int nt = 0; nt < 8; nt++) {
            int j = nt * 8 + qr;
            float ki = kinv[j];
            uint32_t bh0, bl0, bh1, bl1;
            split_tf32(ks[j][k0 + qc] * ki,     bh0, bl0);
            split_tf32(ks[j][k0 + qc + 4] * ki, bh1, bl1);
            mma_tf32(acc[nt][0], acc[nt][1], acc[nt][2], acc[nt][3],
                     ah[0], ah[1], ah[2], ah[3], bh0, bh1);
            mma_tf32(acc[nt][0], acc[nt][1], acc[nt][2], acc[nt][3],
                     ah[0], ah[1], ah[2], ah[3], bl0, bl1);
            mma_tf32(acc[nt][0], acc[nt][1], acc[nt][2], acc[nt][3],
                     al[0], al[1], al[2], al[3], bh0, bh1);
        }
    }

    float scl = sscale;
    int labi0 = lab[i0], labi1 = lab[i1];
    const float* rpb = g_rpb + (hd << 12);
    float mx0 = -1e30f, mx1 = -1e30f;
#pragma unroll
    for (int nt = 0; nt < 8; nt++) {
#pragma unroll
        for (int e = 0; e < 2; e++) {
            int j = nt * 8 + 2 * qc + e;
            int labj = lab[j];
            float s0 = acc[nt][e] * scl + rpb[(i0 << 6) + j];
            if (labi0 != labj) s0 -= 200.f;
            float s1 = acc[nt][2 + e] * scl + rpb[(i1 << 6) + j];
            if (labi1 != labj) s1 -= 200.f;
            acc[nt][e] = s0; acc[nt][2 + e] = s1;
            mx0 = fmaxf(mx0, s0); mx1 = fmaxf(mx1, s1);
        }
    }
    mx0 = fmaxf(mx0, __shfl_xor_sync(0xffffffffu, mx0, 1));
    mx0 = fmaxf(mx0, __shfl_xor_sync(0xffffffffu, mx0, 2));
    mx1 = fmaxf(mx1, __shfl_xor_sync(0xffffffffu, mx1, 1));
    mx1 = fmaxf(mx1, __shfl_xor_sync(0xffffffffu, mx1, 2));
    float sum0 = 0.f, sum1 = 0.f;
#pragma unroll
    for (int nt = 0; nt < 8; nt++) {
#pragma unroll
        for (int e = 0; e < 2; e++) {
            float e0 = __expf(acc[nt][e] - mx0);
            float e1 = __expf(acc[nt][2 + e] - mx1);
            acc[nt][e] = e0; acc[nt][2 + e] = e1;
            sum0 += e0; sum1 += e1;
        }
    }
    sum0 += __shfl_xor_sync(0xffffffffu, sum0, 1);
    sum0 += __shfl_xor_sync(0xffffffffu, sum0, 2);
    sum1 += __shfl_xor_sync(0xffffffffu, sum1, 1);
    sum1 += __shfl_xor_sync(0xffffffffu, sum1, 2);
    float r0 = 1.f / sum0, r1 = 1.f / sum1;
#pragma unroll
    for (int nt = 0; nt < 8; nt++) {
        int j = nt * 8 + 2 * qc;
        ps[i0][j]     = acc[nt][0] * r0;
        ps[i0][j + 1] = acc[nt][1] * r0;
        ps[i1][j]     = acc[nt][2] * r1;
        ps[i1][j + 1] = acc[nt][3] * r1;
    }
    __syncwarp();

    float o[4][4];
#pragma unroll
    for (int nt = 0; nt < 4; nt++)
#pragma unroll
        for (int t = 0; t < 4; t++) o[nt][t] = 0.f;

#pragma unroll
    for (int kt = 0; kt < 8; kt++) {
        int k0 = kt * 8;
        uint32_t ah[4], al[4];
        split_tf32(ps[i0][k0 + qc],     ah[0], al[0]);
        split_tf32(ps[i1][k0 + qc],     ah[1], al[1]);
        split_tf32(ps[i0][k0 + qc + 4], ah[2], al[2]);
        split_tf32(ps[i1][k0 + qc + 4], ah[3], al[3]);
#pragma unroll
        for (int nt = 0; nt < 4; nt++) {
            int d = nt * 8 + qr;
            uint32_t bh0, bl0, bh1, bl1;
            split_tf32(vs[k0 + qc][d],     bh0, bl0);
            split_tf32(vs[k0 + qc + 4][d], bh1, bl1);
            mma_tf32(o[nt][0], o[nt][1], o[nt][2], o[nt][3],
                     ah[0], ah[1], ah[2], ah[3], bh0, bh1);
            mma_tf32(o[nt][0], o[nt][1], o[nt][2], o[nt][3],
                     ah[0], ah[1], ah[2], ah[3], bl0, bl1);
            mma_tf32(o[nt][0], o[nt][1], o[nt][2], o[nt][3],
                     al[0], al[1], al[2], al[3], bh0, bh1);
        }
    }

    float* ob0 = g_ctx + ((long)(w * 64 + i0)) * CC + (hd << 5);
    float* ob1 = g_ctx + ((long)(w * 64 + i1)) * CC + (hd << 5);
#pragma unroll
    for (int nt = 0; nt < 4; nt++) {
        int d = nt * 8 + 2 * qc;
        *(float2*)(ob0 + d) = make_float2(o[nt][0], o[nt][1]);
        *(float2*)(ob1 + d) = make_float2(o[nt][2], o[nt][3]);
    }
}

// ======================= LayerNorm + residual =======================
__global__ void __launch_bounds__(256) k_ln_add(
    const float* __restrict__ xres, const float* __restrict__ xln,
    const float* __restrict__ g, const float* __restrict__ b,
    float* __restrict__ out) {
    int t = blockIdx.x * 8 + (threadIdx.x >> 5);
    int lane = threadIdx.x & 31;
    const float* row = xln + t * CC;
    float v[6];
    float sum = 0.f;
#pragma unroll
    for (int i = 0; i < 6; i++) { v[i] = row[lane + 32 * i]; sum += v[i]; }
#pragma unroll
    for (int o = 16; o > 0; o >>= 1) sum += __shfl_xor_sync(0xffffffffu, sum, o);
    float mu = sum * (1.0f / CC);
    float vs = 0.f;
#pragma unroll
    for (int i = 0; i < 6; i++) { float d = v[i] - mu; vs += d * d; }
#pragma unroll
    for (int o = 16; o > 0; o >>= 1) vs += __shfl_xor_sync(0xffffffffu, vs, o);
    float inv = rsqrtf(vs * (1.0f / CC) + 1e-5f);
#pragma unroll
    for (int i = 0; i < 6; i++) {
        int ch = lane + 32 * i;
        out[t * CC + ch] = xres[t * CC + ch] + (v[i] - mu) * inv * g[ch] + b[ch];
    }
}

// ======================= launch =======================
extern "C" void kernel_launch(void* const* d_in, const int* in_sizes, int n_in,
                              void* d_out, int out_size) {
    const float* hidden = (const float*)d_in[0];
    const float* q_w    = (const float*)d_in[1];
    const float* q_b    = (const float*)d_in[2];
    const float* k_w    = (const float*)d_in[3];
    const float* v_w    = (const float*)d_in[4];
    const float* v_b    = (const float*)d_in[5];
    const float* lscale = (const float*)d_in[6];
    const float* cpb_w1 = (const float*)d_in[7];
    const float* cpb_b1 = (const float*)d_in[8];
    const float* cpb_w2 = (const float*)d_in[9];
    const float* proj_w = (const float*)d_in[10];
    const float* proj_b = (const float*)d_in[11];
    const float* ln1_g  = (const float*)d_in[12];
    const float* ln1_b  = (const float*)d_in[13];
    const float* fc1_w  = (const float*)d_in[14];
    const float* fc1_b  = (const float*)d_in[15];
    const float* fc2_w  = (const float*)d_in[16];
    const float* fc2_b  = (const float*)d_in[17];
    const float* ln2_g  = (const float*)d_in[18];
    const float* ln2_b  = (const float*)d_in[19];
    float* out = (float*)d_out;

    float* gh; float* gxa; float* gmlp;
    cudaGetSymbolAddress((void**)&gh, g_h);
    cudaGetSymbolAddress((void**)&gxa, g_xattn);
    cudaGetSymbolAddress((void**)&gmlp, g_mlp);

    const int SMB = SMEM_FLOATS * 4;   // 92160 bytes
    cudaFuncSetAttribute(k_g<0>, cudaFuncAttributeMaxDynamicSharedMemorySize, SMB);
    cudaFuncSetAttribute(k_g<1>, cudaFuncAttributeMaxDynamicSharedMemorySize, SMB);
    cudaFuncSetAttribute(k_g<2>, cudaFuncAttributeMaxDynamicSharedMemorySize, SMB);
    cudaFuncSetAttribute(k_g<3>, cudaFuncAttributeMaxDynamicSharedMemorySize, SMB);

    k_tr<<<1152, 256>>>(q_w, k_w, v_w, proj_w, fc1_w, fc2_w);
    k_cpb<<<225, 512>>>(cpb_w1, cpb_b1, cpb_w2);
    k_rpb<<<(NHEADS * NTOK * NTOK + 255) / 256, 256>>>();
    k_g<0><<<dim3(1152, 3), 512, SMB>>>(hidden, q_b, v_b);
    k_attn<<<dim3(NWIN, NHEADS), 128>>>(lscale);
    k_g<1><<<dim3(1152, 1), 512, SMB>>>(nullptr, proj_b, nullptr);
    k_ln_add<<<TT / 8, 256>>>(hidden, gxa, ln1_g, ln1_b, gh);
    k_g<2><<<dim3(1152, 2), 512, SMB>>>(nullptr, fc1_b, nullptr);
    k_g<3><<<dim3(1152, 1), 512, SMB>>>(nullptr, fc2_b, nullptr);
    k_ln_add<<<TT / 8, 256>>>(gh, gmlp, ln2_g, ln2_b, out);
}